// round 8
// baseline (speedup 1.0000x reference)
#include <cuda_runtime.h>
#include <cstdint>

// Output layout:
//   [0,       N*D)      mean_messages (float)
//   [N*D,     N*D+N)    last_timestamps (float)
//   [N*D+N,   N*D+2N)   counts (float)

#define MAX_B      (1 << 21)
#define MAX_N      (1 << 18)
#define THREADS    256
#define SCAN_CHUNK 1024                    // elements per scan block (256 thr x 4)
#define MAX_NBS    (MAX_N / SCAN_CHUNK)    // 256

// Single memset zeroes: barrier counter, lookback state, histogram.
#define STATE_OFF  64
#define HIST_OFF   (64 + MAX_NBS)
__device__ __align__(16) unsigned g_zero_region[HIST_OFF + MAX_N];
#define G_BARRIER  (g_zero_region[0])
#define G_STATE    (g_zero_region + STATE_OFF)
#define G_HIST     ((int*)(g_zero_region + HIST_OFF))

__device__ int g_off[MAX_N];
__device__ int g_cur[MAX_N];
__device__ int g_order[MAX_B];

// ---------------- software grid barrier (all blocks resident) --------------
__device__ __forceinline__ void grid_barrier(unsigned gen, unsigned nb) {
    __syncthreads();
    if (threadIdx.x == 0) {
        __threadfence();
        atomicAdd(&G_BARRIER, 1u);
        unsigned target = gen * nb;
        while (atomicAdd(&G_BARRIER, 0u) < target) __nanosleep(64);
        __threadfence();
    }
    __syncthreads();
}

// ---------------- block exclusive scan (nwarps <= 32) ----------------------
__device__ __forceinline__ int block_excl_scan(int v, int tid, int nwarps,
                                               int* total) {
    int lane = tid & 31, wid = tid >> 5;
    __shared__ int wsum[32];
    int inc = v;
    #pragma unroll
    for (int d = 1; d < 32; d <<= 1) {
        int t = __shfl_up_sync(0xffffffffu, inc, d);
        if (lane >= d) inc += t;
    }
    if (lane == 31) wsum[wid] = inc;
    __syncthreads();
    if (wid == 0) {
        int w = (lane < nwarps) ? wsum[lane] : 0;
        #pragma unroll
        for (int d = 1; d < 32; d <<= 1) {
            int t = __shfl_up_sync(0xffffffffu, w, d);
            if (lane >= d) w += t;
        }
        wsum[lane] = w;
    }
    __syncthreads();
    int excl = inc - v + (wid > 0 ? wsum[wid - 1] : 0);
    if (total) *total = wsum[nwarps - 1];
    return excl;
}

// ---------------- fully fused: hist -> scan -> bin -> sum ------------------
__global__ void __launch_bounds__(THREADS, 6)
fused_kernel(const int4* __restrict__ ids4, int B4,
             const int* __restrict__ ids, int B, int N, int NBS,
             const float4* __restrict__ messages4,  // [B, Dq]
             const float* __restrict__ ts,          // [B]
             float4* __restrict__ sums4,            // [N, Dq]
             float* __restrict__ last_ts,           // [N]
             float* __restrict__ counts,            // [N]
             int Dq /* = D/4 = 64 */) {
    const int tid = threadIdx.x;
    const int bid = blockIdx.x;
    const unsigned nb = gridDim.x;
    const int stride = nb * THREADS;
    const int nwarps = THREADS >> 5;

    // ---- phase 1: histogram (grid-stride) ----
    for (int i = bid * THREADS + tid; i < B4; i += stride) {
        int4 v = ids4[i];
        atomicAdd(&G_HIST[v.x], 1);
        atomicAdd(&G_HIST[v.y], 1);
        atomicAdd(&G_HIST[v.z], 1);
        atomicAdd(&G_HIST[v.w], 1);
    }
    if (bid == 0 && tid < (B - B4 * 4))
        atomicAdd(&G_HIST[ids[B4 * 4 + tid]], 1);
    grid_barrier(1, nb);

    // ---- phase 2: decoupled-lookback exclusive scan -> g_off, g_cur ----
    if (bid < NBS) {
        int base = bid * SCAN_CHUNK;
        int i0 = base + tid * 4;
        int4 h = make_int4(0, 0, 0, 0);
        if (i0 + 3 < N) {
            h = *(const int4*)&G_HIST[i0];
        } else {
            if (i0     < N) h.x = G_HIST[i0];
            if (i0 + 1 < N) h.y = G_HIST[i0 + 1];
            if (i0 + 2 < N) h.z = G_HIST[i0 + 2];
            if (i0 + 3 < N) h.w = G_HIST[i0 + 3];
        }
        int s = h.x + h.y + h.z + h.w;
        int tot;
        int excl = block_excl_scan(s, tid, nwarps, &tot);

        __shared__ int s_prev;
        if (tid == 0) {
            atomicExch(&G_STATE[bid], (1u << 30) | (unsigned)tot);
            int prev = 0;
            for (int j = bid - 1; j >= 0; ) {
                unsigned st;
                do { st = atomicAdd(&G_STATE[j], 0u); } while ((st >> 30) == 0u);
                prev += (int)(st & 0x3FFFFFFFu);
                if ((st >> 30) == 2u) break;
                j--;
            }
            atomicExch(&G_STATE[bid], (2u << 30) | (unsigned)(prev + tot));
            s_prev = prev;
        }
        __syncthreads();
        int o = s_prev + excl;
        if (i0     < N) { g_off[i0]     = o;                 g_cur[i0]     = o; }
        o += h.x;
        if (i0 + 1 < N) { g_off[i0 + 1] = o;                 g_cur[i0 + 1] = o; }
        o += h.y;
        if (i0 + 2 < N) { g_off[i0 + 2] = o;                 g_cur[i0 + 2] = o; }
        o += h.z;
        if (i0 + 3 < N) { g_off[i0 + 3] = o;                 g_cur[i0 + 3] = o; }
    }
    grid_barrier(2, nb);

    // ---- phase 3: bin event indices (grid-stride) ----
    for (int i = bid * THREADS + tid; i < B4; i += stride) {
        int4 v = ids4[i];
        int e = i * 4;
        g_order[atomicAdd(&g_cur[v.x], 1)] = e;
        g_order[atomicAdd(&g_cur[v.y], 1)] = e + 1;
        g_order[atomicAdd(&g_cur[v.z], 1)] = e + 2;
        g_order[atomicAdd(&g_cur[v.w], 1)] = e + 3;
    }
    if (bid == 0 && tid < (B - B4 * 4)) {
        int e = B4 * 4 + tid;
        g_order[atomicAdd(&g_cur[ids[e]], 1)] = e;
    }
    grid_barrier(3, nb);

    // ---- phase 4: gather-sum, one warp per node (grid-stride), unroll x2 --
    const int lane = tid & 31;
    const int warps_total = (int)nb * nwarps;
    for (int n = bid * nwarps + (tid >> 5); n < N; n += warps_total) {
        int c = G_HIST[n];
        int start = g_off[n];

        float4 a0 = make_float4(0.f, 0.f, 0.f, 0.f);
        float4 a1 = make_float4(0.f, 0.f, 0.f, 0.f);
        int emax = -1;

        for (int base = 0; base < c; base += 32) {
            int m = min(32, c - base);
            int idx = (lane < m) ? __ldg(&g_order[start + base + lane]) : -1;
            emax = max(emax, idx);

            int k = 0;
            for (; k + 2 <= m; k += 2) {
                int e0 = __shfl_sync(0xffffffffu, idx, k);
                int e1 = __shfl_sync(0xffffffffu, idx, k + 1);
                const float4* row0 = messages4 + (long long)e0 * Dq;
                const float4* row1 = messages4 + (long long)e1 * Dq;
                float4 r00 = __ldg(&row0[lane]);
                float4 r01 = __ldg(&row0[lane + 32]);
                float4 r10 = __ldg(&row1[lane]);
                float4 r11 = __ldg(&row1[lane + 32]);
                a0.x += r00.x; a0.y += r00.y; a0.z += r00.z; a0.w += r00.w;
                a1.x += r01.x; a1.y += r01.y; a1.z += r01.z; a1.w += r01.w;
                a0.x += r10.x; a0.y += r10.y; a0.z += r10.z; a0.w += r10.w;
                a1.x += r11.x; a1.y += r11.y; a1.z += r11.z; a1.w += r11.w;
            }
            if (k < m) {
                int e0 = __shfl_sync(0xffffffffu, idx, k);
                const float4* row0 = messages4 + (long long)e0 * Dq;
                float4 r00 = __ldg(&row0[lane]);
                float4 r01 = __ldg(&row0[lane + 32]);
                a0.x += r00.x; a0.y += r00.y; a0.z += r00.z; a0.w += r00.w;
                a1.x += r01.x; a1.y += r01.y; a1.z += r01.z; a1.w += r01.w;
            }
        }

        #pragma unroll
        for (int d = 16; d > 0; d >>= 1)
            emax = max(emax, __shfl_xor_sync(0xffffffffu, emax, d));

        float inv = 1.0f / fmaxf((float)c, 1.0f);
        a0.x *= inv; a0.y *= inv; a0.z *= inv; a0.w *= inv;
        a1.x *= inv; a1.y *= inv; a1.z *= inv; a1.w *= inv;

        float4* dst = sums4 + (long long)n * Dq;
        dst[lane]      = a0;
        dst[lane + 32] = a1;
        if (lane == 0) {
            counts[n]  = (float)c;
            last_ts[n] = (c > 0) ? __ldg(&ts[emax]) : 0.0f;
        }
    }
}

extern "C" void kernel_launch(void* const* d_in, const int* in_sizes, int n_in,
                              void* d_out, int out_size) {
    const int*   node_ids   = (const int*)  d_in[0];
    const float* messages   = (const float*)d_in[1];
    const float* timestamps = (const float*)d_in[2];

    const int B   = in_sizes[0];
    const int D   = in_sizes[1] / B;            // 256
    const int N   = out_size / (D + 2);         // 100000
    const int Dq  = D / 4;                      // 64
    const int B4  = B / 4;
    const int NBS = (N + SCAN_CHUNK - 1) / SCAN_CHUNK;

    float* out     = (float*)d_out;
    float* sums    = out;                      // [N, D]
    float* last_ts = out + (long long)N * D;   // [N]
    float* counts  = last_ts + N;              // [N]

    // Deadlock-safe persistent grid: all blocks simultaneously resident.
    int dev = 0, nsm = 148, max_blk = 6;
    cudaGetDevice(&dev);
    cudaDeviceGetAttribute(&nsm, cudaDevAttrMultiProcessorCount, dev);
    cudaOccupancyMaxActiveBlocksPerMultiprocessor(&max_blk, fused_kernel,
                                                  THREADS, 0);
    if (max_blk > 6) max_blk = 6;
    if (max_blk < 1) max_blk = 1;
    int grid = nsm * max_blk;

    void* zr_ptr = nullptr;
    cudaGetSymbolAddress(&zr_ptr, g_zero_region);

    // 1. zero barrier + lookback state + histogram (single graph memset node)
    cudaMemsetAsync(zr_ptr, 0, (size_t)(HIST_OFF + N) * sizeof(unsigned), 0);

    // 2. everything else in one persistent kernel
    fused_kernel<<<grid, THREADS>>>((const int4*)node_ids, B4, node_ids, B,
                                    N, NBS, (const float4*)messages,
                                    timestamps, (float4*)sums, last_ts,
                                    counts, Dq);
}